// round 9
// baseline (speedup 1.0000x reference)
#include <cuda_runtime.h>
#include <cuda_bf16.h>
#include <cstdint>

// Problem constants (fixed by the dataset's setup_inputs)
#define NNODES 100000
#define NEDGES 50000
#define EDGESZ 16
#define NMEMB  (NEDGES * EDGESZ)   // 800000
#define DIM    128

// Scratch (allocation-free rule: __device__ globals)
__device__ float g_w2[NNODES];
__device__ float g_edge_sum[(size_t)NEDGES * DIM];
__device__ float g_AH[(size_t)NNODES * DIM];
__device__ int   g_deg[NNODES];
__device__ int   g_cnt[NNODES];
__device__ int   g_off[NNODES];
__device__ int   g_elist[NMEMB];   // node -> list of incident edges
__device__ int   g_ctr;

// ---------------------------------------------------------------------------
// packed f32x2 helpers
// ---------------------------------------------------------------------------
__device__ __forceinline__ void fma2(unsigned long long& d,
                                     unsigned long long a, unsigned long long b)
{
    asm("fma.rn.f32x2 %0, %1, %2, %0;" : "+l"(d) : "l"(a), "l"(b));
}
__device__ __forceinline__ unsigned long long pk2(float lo, float hi)
{
    unsigned long long r;
    asm("mov.b64 %0, {%1, %2};" : "=l"(r) : "f"(lo), "f"(hi));
    return r;
}
__device__ __forceinline__ void unpk2(float& lo, float& hi, unsigned long long v)
{
    asm("mov.b64 {%0, %1}, %2;" : "=f"(lo), "=f"(hi) : "l"(v));
}

// ---------------------------------------------------------------------------
// Kernel W: per-node MLP -> w2[n]; zero deg/cnt/ctr
// ---------------------------------------------------------------------------
__global__ __launch_bounds__(256) void kW(
    const float* __restrict__ iw,
    const float* __restrict__ fc1w, const float* __restrict__ fc1b,
    const float* __restrict__ fc2w, const float* __restrict__ fc2b,
    const float* __restrict__ fc3w, const float* __restrict__ fc3b)
{
    int n = blockIdx.x * 256 + threadIdx.x;
    if (n == 0) g_ctr = 0;
    if (n >= NNODES) return;
    float x0 = iw[n * 2 + 0];
    float x1 = iw[n * 2 + 1];
    float h1[10];
#pragma unroll
    for (int j = 0; j < 10; j++)
        h1[j] = fmaxf(0.f, fmaf(x0, fc1w[j], fmaf(x1, fc1w[10 + j], fc1b[j])));
    float h2[5];
#pragma unroll
    for (int j = 0; j < 5; j++) {
        float s = fc2b[j];
#pragma unroll
        for (int k = 0; k < 10; k++) s = fmaf(h1[k], fc2w[k * 5 + j], s);
        h2[j] = fmaxf(0.f, s);
    }
    float z = fc3b[0];
#pragma unroll
    for (int k = 0; k < 5; k++) z = fmaf(h2[k], fc3w[k], z);
    g_w2[n] = 1.f / (1.f + expf(-z));
    g_deg[n] = 0;
    g_cnt[n] = 0;
}

// ---------------------------------------------------------------------------
// Kernel B: edge_sum[e] = sum_m (H[m]*w2[m]); node-degree histogram.
// ---------------------------------------------------------------------------
__global__ __launch_bounds__(128) void kB(const int* __restrict__ mn,
                                          const float* __restrict__ H)
{
    int e = blockIdx.x;
    __shared__ int   mem[EDGESZ];
    __shared__ float w2e[EDGESZ];
    int t = threadIdx.x;
    if (t < EDGESZ) {
        int node = mn[e * EDGESZ + t];
        mem[t] = node;
        w2e[t] = g_w2[node];
        atomicAdd(&g_deg[node], 1);
    }
    __syncthreads();
    float s = 0.f;
#pragma unroll
    for (int i = 0; i < EDGESZ; i++)
        s = __fadd_rn(s, __fmul_rn(H[(size_t)mem[i] * DIM + t], w2e[i]));
    g_edge_sum[(size_t)e * DIM + t] = s;
}

// ---------------------------------------------------------------------------
// Kernel Off: per-node segment offsets via warp-aggregated atomic counter
// ---------------------------------------------------------------------------
__global__ __launch_bounds__(256) void kOff()
{
    int n = blockIdx.x * 256 + threadIdx.x;
    int lane = threadIdx.x & 31;
    int deg = (n < NNODES) ? g_deg[n] : 0;
    int x = deg;
#pragma unroll
    for (int o = 1; o < 32; o <<= 1) {
        int y = __shfl_up_sync(0xffffffffu, x, o);
        if (lane >= o) x += y;
    }
    int total = __shfl_sync(0xffffffffu, x, 31);
    int base = 0;
    if (lane == 0) base = atomicAdd(&g_ctr, total);
    base = __shfl_sync(0xffffffffu, base, 0);
    if (n < NNODES) g_off[n] = base + x - deg;
}

// ---------------------------------------------------------------------------
// Scatter: build node -> incident-edge list (edge id == membership >> 4)
// ---------------------------------------------------------------------------
__global__ __launch_bounds__(256) void kScat(const int* __restrict__ mn)
{
    int m = blockIdx.x * 256 + threadIdx.x;
    if (m >= NMEMB) return;
    int node = mn[m];
    int pos = g_off[node] + atomicAdd(&g_cnt[node], 1);
    g_elist[pos] = m >> 4;
}

// ---------------------------------------------------------------------------
// Sort each node's edge segment ascending -> deterministic gather order
// ---------------------------------------------------------------------------
__global__ __launch_bounds__(256) void kSort()
{
    int n = blockIdx.x * 256 + threadIdx.x;
    if (n >= NNODES) return;
    int st = g_off[n];
    int deg = g_deg[n];
    for (int i = 1; i < deg; i++) {
        int key = g_elist[st + i];
        int j = i - 1;
        while (j >= 0 && g_elist[st + j] > key) {
            g_elist[st + j + 1] = g_elist[st + j];
            j--;
        }
        g_elist[st + j + 1] = key;
    }
}

// ---------------------------------------------------------------------------
// Kernel F: per-node gather -> new_signal -> double rowsum -> AH
// grid = NNODES blocks x 128 threads (one node per block, col = thread)
// ---------------------------------------------------------------------------
__global__ __launch_bounds__(128) void kF(const float* __restrict__ H)
{
    int n = blockIdx.x, t = threadIdx.x;
    int deg = g_deg[n];
    int st  = g_off[n];
    const float inv15 = 1.f / 15.f;

    float s = 0.f;
    int j = 0;
    for (; j + 4 <= deg; j += 4) {
        float v0 = g_edge_sum[(size_t)g_elist[st + j + 0] * DIM + t];
        float v1 = g_edge_sum[(size_t)g_elist[st + j + 1] * DIM + t];
        float v2 = g_edge_sum[(size_t)g_elist[st + j + 2] * DIM + t];
        float v3 = g_edge_sum[(size_t)g_elist[st + j + 3] * DIM + t];
        s = __fadd_rn(__fadd_rn(__fadd_rn(__fadd_rn(s, v0), v1), v2), v3);
    }
    for (; j < deg; j++)
        s = __fadd_rn(s, g_edge_sum[(size_t)g_elist[st + j] * DIM + t]);

    size_t off = (size_t)n * DIM + t;
    float nv = fmaf(H[off], 1.f - (float)deg * inv15, s * inv15);

    // double-precision block rowsum
    __shared__ double red[4];
    __shared__ float rinv_s;
    double v = (double)nv;
#pragma unroll
    for (int o = 16; o > 0; o >>= 1)
        v += __shfl_xor_sync(0xffffffffu, v, o);
    if ((t & 31) == 0) red[t >> 5] = v;
    __syncthreads();
    if (t == 0) {
        double rowsum = ((red[0] + red[1]) + red[2]) + red[3];
        rinv_s = (rowsum != 0.0) ? (float)(1.0 / rowsum) : 0.f;
    }
    __syncthreads();
    g_AH[off] = __fmul_rn(nv, rinv_s);
}

// ---------------------------------------------------------------------------
// Kernel E: out = AH @ W + bias, packed f32x2 FFMA
// block = 128 threads handles 32 rows; thread owns output column t
// ---------------------------------------------------------------------------
__global__ __launch_bounds__(128) void kE(const float* __restrict__ W,
                                          const float* __restrict__ bias,
                                          float* __restrict__ out)
{
    __shared__ float sA[32 * DIM];
    int t = threadIdx.x;
    size_t base = (size_t)blockIdx.x * 32 * DIM;
#pragma unroll
    for (int i = 0; i < 32; i++)
        sA[i * DIM + t] = g_AH[base + (size_t)i * DIM + t];
    __syncthreads();

    unsigned long long acc[32];
#pragma unroll
    for (int i = 0; i < 32; i++) acc[i] = 0ull;

#pragma unroll 1
    for (int k = 0; k < DIM; k += 8) {
        unsigned long long wp0 = pk2(W[(k + 0) * DIM + t], W[(k + 1) * DIM + t]);
        unsigned long long wp1 = pk2(W[(k + 2) * DIM + t], W[(k + 3) * DIM + t]);
        unsigned long long wp2 = pk2(W[(k + 4) * DIM + t], W[(k + 5) * DIM + t]);
        unsigned long long wp3 = pk2(W[(k + 6) * DIM + t], W[(k + 7) * DIM + t]);
        const ulonglong2* arow = reinterpret_cast<const ulonglong2*>(sA + k);
#pragma unroll
        for (int i = 0; i < 32; i++) {
            ulonglong2 a0 = arow[i * (DIM / 4)];
            ulonglong2 a1 = arow[i * (DIM / 4) + 1];
            fma2(acc[i], a0.x, wp0);
            fma2(acc[i], a0.y, wp1);
            fma2(acc[i], a1.x, wp2);
            fma2(acc[i], a1.y, wp3);
        }
    }
    float b = bias[t];
#pragma unroll
    for (int i = 0; i < 32; i++) {
        float lo, hi;
        unpk2(lo, hi, acc[i]);
        out[base + (size_t)i * DIM + t] = lo + hi + b;
    }
}

// ---------------------------------------------------------------------------
extern "C" void kernel_launch(void* const* d_in, const int* in_sizes, int n_in,
                              void* d_out, int out_size)
{
    const int*   member_nodes = (const int*)  d_in[0];
    const float* H            = (const float*)d_in[2];
    const float* input_weight = (const float*)d_in[3];
    const float* W            = (const float*)d_in[4];
    const float* bias         = (const float*)d_in[5];
    const float* fc1_w        = (const float*)d_in[6];
    const float* fc1_b        = (const float*)d_in[7];
    const float* fc2_w        = (const float*)d_in[8];
    const float* fc2_b        = (const float*)d_in[9];
    const float* fc3_w        = (const float*)d_in[10];
    const float* fc3_b        = (const float*)d_in[11];
    float* out = (float*)d_out;

    kW<<<(NNODES + 255) / 256, 256>>>(input_weight,
                                      fc1_w, fc1_b, fc2_w, fc2_b, fc3_w, fc3_b);
    kB<<<NEDGES, 128>>>(member_nodes, H);
    kOff<<<(NNODES + 255) / 256, 256>>>();
    kScat<<<(NMEMB + 255) / 256, 256>>>(member_nodes);
    kSort<<<(NNODES + 255) / 256, 256>>>();
    kF<<<NNODES, 128>>>(H);
    kE<<<NNODES / 32, 128>>>(W, bias, out);
}

// round 10
// speedup vs baseline: 1.3481x; 1.3481x over previous
#include <cuda_runtime.h>
#include <cuda_bf16.h>
#include <cstdint>

// Problem constants (fixed by the dataset's setup_inputs)
#define NNODES 100000
#define NEDGES 50000
#define EDGESZ 16
#define NMEMB  (NEDGES * EDGESZ)   // 800000
#define DIM    128

// Scratch (allocation-free rule: __device__ globals)
__device__ float g_w2[NNODES];
__device__ float g_edge_sum[(size_t)NEDGES * DIM];
__device__ float g_AH[(size_t)NNODES * DIM];
__device__ int   g_deg[NNODES];
__device__ int   g_cnt[NNODES];
__device__ int   g_off[NNODES];
__device__ int   g_elist[NMEMB];   // node -> list of incident edges
__device__ int   g_ctr;

// ---------------------------------------------------------------------------
// packed f32x2 helpers
// ---------------------------------------------------------------------------
__device__ __forceinline__ void fma2(unsigned long long& d,
                                     unsigned long long a, unsigned long long b)
{
    asm("fma.rn.f32x2 %0, %1, %2, %0;" : "+l"(d) : "l"(a), "l"(b));
}
__device__ __forceinline__ unsigned long long pk2(float lo, float hi)
{
    unsigned long long r;
    asm("mov.b64 %0, {%1, %2};" : "=l"(r) : "f"(lo), "f"(hi));
    return r;
}
__device__ __forceinline__ void unpk2(float& lo, float& hi, unsigned long long v)
{
    asm("mov.b64 {%0, %1}, %2;" : "=f"(lo), "=f"(hi) : "l"(v));
}

// ---------------------------------------------------------------------------
// Kernel W: per-node MLP -> w2[n]; zero deg/cnt/ctr
// ---------------------------------------------------------------------------
__global__ __launch_bounds__(256) void kW(
    const float* __restrict__ iw,
    const float* __restrict__ fc1w, const float* __restrict__ fc1b,
    const float* __restrict__ fc2w, const float* __restrict__ fc2b,
    const float* __restrict__ fc3w, const float* __restrict__ fc3b)
{
    int n = blockIdx.x * 256 + threadIdx.x;
    if (n == 0) g_ctr = 0;
    if (n >= NNODES) return;
    float x0 = iw[n * 2 + 0];
    float x1 = iw[n * 2 + 1];
    float h1[10];
#pragma unroll
    for (int j = 0; j < 10; j++)
        h1[j] = fmaxf(0.f, fmaf(x0, fc1w[j], fmaf(x1, fc1w[10 + j], fc1b[j])));
    float h2[5];
#pragma unroll
    for (int j = 0; j < 5; j++) {
        float s = fc2b[j];
#pragma unroll
        for (int k = 0; k < 10; k++) s = fmaf(h1[k], fc2w[k * 5 + j], s);
        h2[j] = fmaxf(0.f, s);
    }
    float z = fc3b[0];
#pragma unroll
    for (int k = 0; k < 5; k++) z = fmaf(h2[k], fc3w[k], z);
    g_w2[n] = 1.f / (1.f + expf(-z));
    g_deg[n] = 0;
    g_cnt[n] = 0;
}

// ---------------------------------------------------------------------------
// Kernel B: edge_sum[e] = sum_m (H[m]*w2[m]); node-degree histogram.
// ---------------------------------------------------------------------------
__global__ __launch_bounds__(128) void kB(const int* __restrict__ mn,
                                          const float* __restrict__ H)
{
    int e = blockIdx.x;
    __shared__ int   mem[EDGESZ];
    __shared__ float w2e[EDGESZ];
    int t = threadIdx.x;
    if (t < EDGESZ) {
        int node = mn[e * EDGESZ + t];
        mem[t] = node;
        w2e[t] = g_w2[node];
        atomicAdd(&g_deg[node], 1);
    }
    __syncthreads();
    float s = 0.f;
#pragma unroll
    for (int i = 0; i < EDGESZ; i++)
        s = __fadd_rn(s, __fmul_rn(H[(size_t)mem[i] * DIM + t], w2e[i]));
    g_edge_sum[(size_t)e * DIM + t] = s;
}

// ---------------------------------------------------------------------------
// Kernel Off: per-node segment offsets via warp-aggregated atomic counter
// ---------------------------------------------------------------------------
__global__ __launch_bounds__(256) void kOff()
{
    int n = blockIdx.x * 256 + threadIdx.x;
    int lane = threadIdx.x & 31;
    int deg = (n < NNODES) ? g_deg[n] : 0;
    int x = deg;
#pragma unroll
    for (int o = 1; o < 32; o <<= 1) {
        int y = __shfl_up_sync(0xffffffffu, x, o);
        if (lane >= o) x += y;
    }
    int total = __shfl_sync(0xffffffffu, x, 31);
    int base = 0;
    if (lane == 0) base = atomicAdd(&g_ctr, total);
    base = __shfl_sync(0xffffffffu, base, 0);
    if (n < NNODES) g_off[n] = base + x - deg;
}

// ---------------------------------------------------------------------------
// Scatter: build node -> incident-edge list (edge id == membership >> 4)
// (arrival order racy; kF sorts the segment in smem -> deterministic)
// ---------------------------------------------------------------------------
__global__ __launch_bounds__(256) void kScat(const int* __restrict__ mn)
{
    int m = blockIdx.x * 256 + threadIdx.x;
    if (m >= NMEMB) return;
    int node = mn[m];
    int pos = g_off[node] + atomicAdd(&g_cnt[node], 1);
    g_elist[pos] = m >> 4;
}

// ---------------------------------------------------------------------------
// Kernel F: per-node smem rank-sort of edge segment -> gather -> new_signal
//           -> float rowsum tree -> AH.  One node per block, 128 threads.
// ---------------------------------------------------------------------------
__global__ __launch_bounds__(128) void kF(const float* __restrict__ H)
{
    int n = blockIdx.x, t = threadIdx.x;
    int deg = g_deg[n];
    int st  = g_off[n];
    const float inv15 = 1.f / 15.f;

    // Stable rank-sort of the (racy-ordered) edge segment, in smem.
    __shared__ int se[128];
    __shared__ int ss[128];
    if (t < deg) se[t] = g_elist[st + t];
    __syncthreads();
    if (t < deg) {
        int e = se[t];
        int rank = 0;
        for (int j = 0; j < deg; j++) {
            int ej = se[j];
            rank += (ej < e) || (ej == e && j < t);
        }
        ss[rank] = e;
    }
    __syncthreads();

    // Gather edge sums in ascending-edge order (matches reference segment_sum)
    float s = 0.f;
    int j = 0;
    for (; j + 4 <= deg; j += 4) {
        float v0 = g_edge_sum[(size_t)ss[j + 0] * DIM + t];
        float v1 = g_edge_sum[(size_t)ss[j + 1] * DIM + t];
        float v2 = g_edge_sum[(size_t)ss[j + 2] * DIM + t];
        float v3 = g_edge_sum[(size_t)ss[j + 3] * DIM + t];
        s = __fadd_rn(__fadd_rn(__fadd_rn(__fadd_rn(s, v0), v1), v2), v3);
    }
    for (; j < deg; j++)
        s = __fadd_rn(s, g_edge_sum[(size_t)ss[j] * DIM + t]);

    size_t off = (size_t)n * DIM + t;
    float nv = fmaf(H[off], 1.f - (float)deg * inv15, s * inv15);

    // float rowsum tree (deterministic now that gather order is sorted)
    __shared__ float red[4];
    __shared__ float rinv_s;
    float v = nv;
#pragma unroll
    for (int o = 16; o > 0; o >>= 1)
        v += __shfl_xor_sync(0xffffffffu, v, o);
    if ((t & 31) == 0) red[t >> 5] = v;
    __syncthreads();
    if (t == 0) {
        float rowsum = ((red[0] + red[1]) + red[2]) + red[3];
        rinv_s = (rowsum != 0.f) ? (1.f / rowsum) : 0.f;
    }
    __syncthreads();
    g_AH[off] = __fmul_rn(nv, rinv_s);
}

// ---------------------------------------------------------------------------
// Kernel E: out = AH @ W + bias, packed f32x2 FFMA
// block = 128 threads handles 32 rows; thread owns output column t
// ---------------------------------------------------------------------------
__global__ __launch_bounds__(128) void kE(const float* __restrict__ W,
                                          const float* __restrict__ bias,
                                          float* __restrict__ out)
{
    __shared__ float sA[32 * DIM];
    int t = threadIdx.x;
    size_t base = (size_t)blockIdx.x * 32 * DIM;
#pragma unroll
    for (int i = 0; i < 32; i++)
        sA[i * DIM + t] = g_AH[base + (size_t)i * DIM + t];
    __syncthreads();

    unsigned long long acc[32];
#pragma unroll
    for (int i = 0; i < 32; i++) acc[i] = 0ull;

#pragma unroll 1
    for (int k = 0; k < DIM; k += 8) {
        unsigned long long wp0 = pk2(W[(k + 0) * DIM + t], W[(k + 1) * DIM + t]);
        unsigned long long wp1 = pk2(W[(k + 2) * DIM + t], W[(k + 3) * DIM + t]);
        unsigned long long wp2 = pk2(W[(k + 4) * DIM + t], W[(k + 5) * DIM + t]);
        unsigned long long wp3 = pk2(W[(k + 6) * DIM + t], W[(k + 7) * DIM + t]);
        const ulonglong2* arow = reinterpret_cast<const ulonglong2*>(sA + k);
#pragma unroll
        for (int i = 0; i < 32; i++) {
            ulonglong2 a0 = arow[i * (DIM / 4)];
            ulonglong2 a1 = arow[i * (DIM / 4) + 1];
            fma2(acc[i], a0.x, wp0);
            fma2(acc[i], a0.y, wp1);
            fma2(acc[i], a1.x, wp2);
            fma2(acc[i], a1.y, wp3);
        }
    }
    float b = bias[t];
#pragma unroll
    for (int i = 0; i < 32; i++) {
        float lo, hi;
        unpk2(lo, hi, acc[i]);
        out[base + (size_t)i * DIM + t] = lo + hi + b;
    }
}

// ---------------------------------------------------------------------------
extern "C" void kernel_launch(void* const* d_in, const int* in_sizes, int n_in,
                              void* d_out, int out_size)
{
    const int*   member_nodes = (const int*)  d_in[0];
    const float* H            = (const float*)d_in[2];
    const float* input_weight = (const float*)d_in[3];
    const float* W            = (const float*)d_in[4];
    const float* bias         = (const float*)d_in[5];
    const float* fc1_w        = (const float*)d_in[6];
    const float* fc1_b        = (const float*)d_in[7];
    const float* fc2_w        = (const float*)d_in[8];
    const float* fc2_b        = (const float*)d_in[9];
    const float* fc3_w        = (const float*)d_in[10];
    const float* fc3_b        = (const float*)d_in[11];
    float* out = (float*)d_out;

    kW<<<(NNODES + 255) / 256, 256>>>(input_weight,
                                      fc1_w, fc1_b, fc2_w, fc2_b, fc3_w, fc3_b);
    kB<<<NEDGES, 128>>>(member_nodes, H);
    kOff<<<(NNODES + 255) / 256, 256>>>();
    kScat<<<(NMEMB + 255) / 256, 256>>>(member_nodes);
    kF<<<NNODES, 128>>>(H);
    kE<<<NNODES / 32, 128>>>(W, bias, out);
}